// round 1
// baseline (speedup 1.0000x reference)
#include <cuda_runtime.h>
#include <math.h>

#define S_TOK 4096
#define NH    12
#define HD    64
#define NROWS (S_TOK*NH)
#define QT    128
#define KT    64

// Scratch (allocation-free rule: __device__ globals)
__device__ float g_k[(size_t)NH*S_TOK*HD];
__device__ float g_v[(size_t)NH*S_TOK*HD];
__device__ float g_P[4][16];
__device__ float g_PT[4][16];
__device__ float g_Pinv[4][16];
__device__ float g_cos[32][8];
__device__ float g_sin[32][8];

__device__ __forceinline__ void mm4(const float* A, const float* B, float* Cm) {
#pragma unroll
    for (int i = 0; i < 4; i++)
#pragma unroll
        for (int j = 0; j < 4; j++) {
            float s = 0.f;
#pragma unroll
            for (int kk = 0; kk < 4; kk++) s += A[i*4+kk] * B[kk*4+j];
            Cm[i*4+j] = s;
        }
}

// ---------------------------------------------------------------------------
// Prep: per-camera matrices + RoPE cos/sin table
// ---------------------------------------------------------------------------
__global__ void prep_kernel(const float* __restrict__ vm, const float* __restrict__ Ks) {
    int t = threadIdx.x;
    if (t < 32) {
        float L = log2f(100.0f);
#pragma unroll
        for (int i = 0; i < 8; i++) {
            float f = exp2f(-L * (float)i / 8.0f);
            float a = (float)t * f;
            float sv, cv;
            sincosf(a, &sv, &cv);
            g_cos[t][i] = cv;
            g_sin[t][i] = sv;
        }
    }
    if (t < 4) {
        int c = t;
        const float* V  = vm + c*16;
        const float* Kc = Ks + c*9;
        float a = Kc[0] * (1.0f/512.0f);
        float b = Kc[4] * (1.0f/512.0f);
        float u = Kc[2] * (1.0f/512.0f) - 0.5f;
        float w = Kc[5] * (1.0f/512.0f) - 0.5f;
        float K4[16] = {a,0,u,0,  0,b,w,0,  0,0,1,0,  0,0,0,1};
        float Vl[16];
#pragma unroll
        for (int i = 0; i < 16; i++) Vl[i] = V[i];
        float P[16];
        mm4(K4, Vl, P);
#pragma unroll
        for (int i = 0; i < 4; i++)
#pragma unroll
            for (int j = 0; j < 4; j++) {
                g_P[c][i*4+j]  = P[i*4+j];
                g_PT[c][i*4+j] = P[j*4+i];
            }
        // invert_SE3(viewmats)
        float Sm[16];
#pragma unroll
        for (int i = 0; i < 3; i++)
#pragma unroll
            for (int j = 0; j < 3; j++) Sm[i*4+j] = Vl[j*4+i];
#pragma unroll
        for (int i = 0; i < 3; i++)
            Sm[i*4+3] = -(Sm[i*4+0]*Vl[3] + Sm[i*4+1]*Vl[7] + Sm[i*4+2]*Vl[11]);
        Sm[12] = 0.f; Sm[13] = 0.f; Sm[14] = 0.f; Sm[15] = 1.f;
        // lift_K(invert_K(Ksn))
        float Ki[16] = {1.0f/a, 0, -u/a, 0,
                        0, 1.0f/b, -w/b, 0,
                        0, 0, 1, 0,
                        0, 0, 0, 1};
        float Pi[16];
        mm4(Sm, Ki, Pi);
#pragma unroll
        for (int i = 0; i < 16; i++) g_Pinv[c][i] = Pi[i];
    }
}

// ---------------------------------------------------------------------------
// Transform one 64-dim row: 4x4 per-chunk projection on dims [0,32),
// forward RoPE on [32,48) (pos_x) and [48,64) (pos_y)
// ---------------------------------------------------------------------------
__device__ __forceinline__ void transform_row_fwd(
    const float* __restrict__ in, float* __restrict__ out,
    const float* M, int px, int py)
{
    float x[64];
    const float4* in4 = (const float4*)in;
#pragma unroll
    for (int i = 0; i < 16; i++) {
        float4 tv = in4[i];
        x[4*i+0] = tv.x; x[4*i+1] = tv.y; x[4*i+2] = tv.z; x[4*i+3] = tv.w;
    }
    float y[64];
#pragma unroll
    for (int g = 0; g < 8; g++)
#pragma unroll
        for (int i = 0; i < 4; i++)
            y[g*4+i] = M[i*4+0]*x[g*4+0] + M[i*4+1]*x[g*4+1]
                     + M[i*4+2]*x[g*4+2] + M[i*4+3]*x[g*4+3];
#pragma unroll
    for (int i = 0; i < 8; i++) {
        float c1 = g_cos[px][i], s1 = g_sin[px][i];
        y[32+i] =  c1*x[32+i] + s1*x[40+i];
        y[40+i] = -s1*x[32+i] + c1*x[40+i];
        float c2 = g_cos[py][i], s2 = g_sin[py][i];
        y[48+i] =  c2*x[48+i] + s2*x[56+i];
        y[56+i] = -s2*x[48+i] + c2*x[56+i];
    }
    float4* out4 = (float4*)out;
#pragma unroll
    for (int i = 0; i < 16; i++)
        out4[i] = make_float4(y[4*i+0], y[4*i+1], y[4*i+2], y[4*i+3]);
}

// ---------------------------------------------------------------------------
// k/v transform: input (s,h,d) row-major -> g_k/g_v in [h][s][d]
// ---------------------------------------------------------------------------
__global__ void transform_kv_kernel(const float* __restrict__ k, const float* __restrict__ v) {
    int r = blockIdx.x * blockDim.x + threadIdx.x;  // r = s*12 + h
    if (r >= NROWS) return;
    int s = r / NH;
    int h = r - s * NH;
    int c  = s >> 10;
    int px = s & 31;
    int py = (s >> 5) & 31;
    float M[16];
#pragma unroll
    for (int i = 0; i < 16; i++) M[i] = g_Pinv[c][i];
    size_t ibase = (size_t)r * HD;
    size_t obase = ((size_t)h * S_TOK + s) * HD;
    transform_row_fwd(k + ibase, g_k + obase, M, px, py);
    transform_row_fwd(v + ibase, g_v + obase, M, px, py);
}

// ---------------------------------------------------------------------------
// Attention: one thread per (query,head). Fuses q transform + epilogue.
// ---------------------------------------------------------------------------
__global__ void __launch_bounds__(QT)
attn_kernel(const float* __restrict__ q, float* __restrict__ out) {
    __shared__ float sK[KT][HD];
    __shared__ float sV[KT][HD];

    const int h  = blockIdx.y;
    const int s  = blockIdx.x * QT + threadIdx.x;
    const int c  = s >> 10;
    const int px = s & 31;
    const int py = (s >> 5) & 31;

    // ---- load + transform q (Pᵀ proj + forward RoPE) ----
    float qv[64];
    {
        float x[64];
        const float4* qr = (const float4*)(q + (size_t)s * (NH*HD) + (size_t)h * HD);
#pragma unroll
        for (int i = 0; i < 16; i++) {
            float4 tv = qr[i];
            x[4*i+0] = tv.x; x[4*i+1] = tv.y; x[4*i+2] = tv.z; x[4*i+3] = tv.w;
        }
        const float* M = g_PT[c];
#pragma unroll
        for (int g = 0; g < 8; g++)
#pragma unroll
            for (int i = 0; i < 4; i++)
                qv[g*4+i] = M[i*4+0]*x[g*4+0] + M[i*4+1]*x[g*4+1]
                          + M[i*4+2]*x[g*4+2] + M[i*4+3]*x[g*4+3];
#pragma unroll
        for (int i = 0; i < 8; i++) {
            float c1 = g_cos[px][i], s1 = g_sin[px][i];
            qv[32+i] =  c1*x[32+i] + s1*x[40+i];
            qv[40+i] = -s1*x[32+i] + c1*x[40+i];
            float c2 = g_cos[py][i], s2 = g_sin[py][i];
            qv[48+i] =  c2*x[48+i] + s2*x[56+i];
            qv[56+i] = -s2*x[48+i] + c2*x[56+i];
        }
    }

    // ---- flash attention over all keys (online softmax) ----
    float m = -INFINITY, l = 0.f;
    float acc[64];
#pragma unroll
    for (int d = 0; d < 64; d++) acc[d] = 0.f;
    const float k2 = 0.125f * 1.4426950408889634f;  // scale * log2(e)

    const float4* kg_base = (const float4*)(g_k + (size_t)h * S_TOK * HD);
    const float4* vg_base = (const float4*)(g_v + (size_t)h * S_TOK * HD);
    float4* sk4 = (float4*)&sK[0][0];
    float4* sv4 = (float4*)&sV[0][0];

#pragma unroll 1
    for (int t = 0; t < S_TOK / KT; t++) {
        const float4* kg = kg_base + (size_t)t * (KT*HD/4);
        const float4* vg = vg_base + (size_t)t * (KT*HD/4);
#pragma unroll
        for (int i = 0; i < (KT*HD/4)/QT; i++) {
            sk4[threadIdx.x + i*QT] = kg[threadIdx.x + i*QT];
            sv4[threadIdx.x + i*QT] = vg[threadIdx.x + i*QT];
        }
        __syncthreads();

#pragma unroll 1
        for (int j = 0; j < KT; j++) {
            const float4* kr = (const float4*)&sK[j][0];
            float dp0 = 0.f, dp1 = 0.f, dp2 = 0.f, dp3 = 0.f;
#pragma unroll
            for (int i = 0; i < 16; i += 4) {
                float4 a0 = kr[i+0], a1 = kr[i+1], a2 = kr[i+2], a3 = kr[i+3];
                dp0 = fmaf(qv[4*i+ 0], a0.x, fmaf(qv[4*i+ 1], a0.y, fmaf(qv[4*i+ 2], a0.z, fmaf(qv[4*i+ 3], a0.w, dp0))));
                dp1 = fmaf(qv[4*i+ 4], a1.x, fmaf(qv[4*i+ 5], a1.y, fmaf(qv[4*i+ 6], a1.z, fmaf(qv[4*i+ 7], a1.w, dp1))));
                dp2 = fmaf(qv[4*i+ 8], a2.x, fmaf(qv[4*i+ 9], a2.y, fmaf(qv[4*i+10], a2.z, fmaf(qv[4*i+11], a2.w, dp2))));
                dp3 = fmaf(qv[4*i+12], a3.x, fmaf(qv[4*i+13], a3.y, fmaf(qv[4*i+14], a3.z, fmaf(qv[4*i+15], a3.w, dp3))));
            }
            float sdot = (dp0 + dp1) + (dp2 + dp3);

            float p;
            float mnew = fmaxf(m, sdot);
            if (mnew > m) {
                float rs = exp2f((m - mnew) * k2);  // 0 on first key (m=-inf)
                l *= rs;
#pragma unroll
                for (int d = 0; d < 64; d++) acc[d] *= rs;
                m = mnew;
                p = 1.0f;
            } else {
                p = exp2f((sdot - m) * k2);
            }
            l += p;

            const float4* vr = (const float4*)&sV[j][0];
#pragma unroll
            for (int i = 0; i < 16; i++) {
                float4 vv = vr[i];
                acc[4*i+0] = fmaf(p, vv.x, acc[4*i+0]);
                acc[4*i+1] = fmaf(p, vv.y, acc[4*i+1]);
                acc[4*i+2] = fmaf(p, vv.z, acc[4*i+2]);
                acc[4*i+3] = fmaf(p, vv.w, acc[4*i+3]);
            }
        }
        __syncthreads();
    }

    float inv = 1.0f / l;
#pragma unroll
    for (int d = 0; d < 64; d++) acc[d] *= inv;

    // ---- epilogue: to() = P proj + inverse RoPE ----
    float y[64];
    {
        const float* M = g_P[c];
#pragma unroll
        for (int g = 0; g < 8; g++)
#pragma unroll
            for (int i = 0; i < 4; i++)
                y[g*4+i] = M[i*4+0]*acc[g*4+0] + M[i*4+1]*acc[g*4+1]
                         + M[i*4+2]*acc[g*4+2] + M[i*4+3]*acc[g*4+3];
#pragma unroll
        for (int i = 0; i < 8; i++) {
            float c1 = g_cos[px][i], s1 = g_sin[px][i];
            y[32+i] = c1*acc[32+i] - s1*acc[40+i];
            y[40+i] = s1*acc[32+i] + c1*acc[40+i];
            float c2 = g_cos[py][i], s2 = g_sin[py][i];
            y[48+i] = c2*acc[48+i] - s2*acc[56+i];
            y[56+i] = s2*acc[48+i] + c2*acc[56+i];
        }
    }
    float4* o4 = (float4*)(out + (size_t)s * (NH*HD) + (size_t)h * HD);
#pragma unroll
    for (int i = 0; i < 16; i++)
        o4[i] = make_float4(y[4*i+0], y[4*i+1], y[4*i+2], y[4*i+3]);
}

// ---------------------------------------------------------------------------
extern "C" void kernel_launch(void* const* d_in, const int* in_sizes, int n_in,
                              void* d_out, int out_size) {
    const float* q  = (const float*)d_in[0];
    const float* k  = (const float*)d_in[1];
    const float* v  = (const float*)d_in[2];
    const float* vm = (const float*)d_in[3];
    const float* Ks = (const float*)d_in[4];
    float* out = (float*)d_out;

    prep_kernel<<<1, 32>>>(vm, Ks);
    transform_kv_kernel<<<(NROWS + 255) / 256, 256>>>(k, v);
    attn_kernel<<<dim3(S_TOK / QT, NH), QT>>>(q, out);
}